// round 2
// baseline (speedup 1.0000x reference)
#include <cuda_runtime.h>
#include <cstdint>

#define BB 8
#define LXX 2048
#define LYY 2048
#define DD 256

// Scratch for projections (no cudaMalloc allowed)
__device__ float g_xp[BB * LXX * DD];
__device__ float g_yp[BB * LYY * DD];

// ---------------------------------------------------------------------------
// Projection: C[m,n] = relu( sum_k A[m,k] * W[n,k] + bias[n] )
// A: [M, 256] row-major, W: [256, 256] row-major (row n = output channel)
// Tile 128x128, BK=16, 256 threads, 8x8 micro-tile.
// which: 0 -> write g_xp, 1 -> write g_yp
// ---------------------------------------------------------------------------
__global__ __launch_bounds__(256, 1)
void proj_kernel(const float* __restrict__ A,
                 const float* __restrict__ W,
                 const float* __restrict__ bias,
                 int which)
{
    __shared__ float As[16][132];  // [k][m], stride 132 keeps 16B alignment
    __shared__ float Bs[16][132];  // [k][n]

    const int tid = threadIdx.x;
    const int tx = tid & 15;
    const int ty = tid >> 4;
    const int row0 = blockIdx.y * 128;
    const int col0 = blockIdx.x * 128;

    float* __restrict__ C = which ? g_yp : g_xp;

    float acc[8][8];
#pragma unroll
    for (int i = 0; i < 8; i++)
#pragma unroll
        for (int j = 0; j < 8; j++) acc[i][j] = 0.0f;

    for (int k0 = 0; k0 < DD; k0 += 16) {
#pragma unroll
        for (int e = 0; e < 8; e++) {
            int elem = tid + e * 256;
            int kk = elem & 15;      // = tid & 15
            int r  = elem >> 4;
            As[kk][r] = A[(size_t)(row0 + r) * DD + k0 + kk];
            Bs[kk][r] = W[(size_t)(col0 + r) * DD + k0 + kk];
        }
        __syncthreads();
#pragma unroll
        for (int kk = 0; kk < 16; kk++) {
            float4 a0 = *(const float4*)&As[kk][ty * 8];
            float4 a1 = *(const float4*)&As[kk][ty * 8 + 4];
            float4 b0 = *(const float4*)&Bs[kk][tx * 8];
            float4 b1 = *(const float4*)&Bs[kk][tx * 8 + 4];
            float a[8] = {a0.x, a0.y, a0.z, a0.w, a1.x, a1.y, a1.z, a1.w};
            float bq[8] = {b0.x, b0.y, b0.z, b0.w, b1.x, b1.y, b1.z, b1.w};
#pragma unroll
            for (int i = 0; i < 8; i++)
#pragma unroll
                for (int j = 0; j < 8; j++)
                    acc[i][j] = fmaf(a[i], bq[j], acc[i][j]);
        }
        __syncthreads();
    }

    // epilogue: bias + relu, vectorized store
    float bv[8];
#pragma unroll
    for (int j = 0; j < 8; j++) bv[j] = bias[col0 + tx * 8 + j];

#pragma unroll
    for (int i = 0; i < 8; i++) {
        int row = row0 + ty * 8 + i;
        float v[8];
#pragma unroll
        for (int j = 0; j < 8; j++) v[j] = fmaxf(acc[i][j] + bv[j], 0.0f);
        float4* dst = (float4*)&C[(size_t)row * DD + col0 + tx * 8];
        dst[0] = make_float4(v[0], v[1], v[2], v[3]);
        dst[1] = make_float4(v[4], v[5], v[6], v[7]);
    }
}

// ---------------------------------------------------------------------------
// Fused attention: per CTA = (batch b, 64-row x tile).
//   S = Xp_tile @ Yp_tile^T (64x64), mask -> -3e38, online softmax,
//   acc += P @ Y_tile, final normalize by row sum.
// 256 threads: 16x16 grid. S micro-tile 4x4 (rows ty*4+i, cols tx*4+j).
// Output micro-tile 4x16 (rows ty*4+i, cols c*16+tx).
// ---------------------------------------------------------------------------
#define TSTRIDE 68   // stride for k-major transposed tiles (16B aligned, low conflict)
#define PSTRIDE 68

#define SM_FLOATS (2 * 256 * TSTRIDE + 64 * 256 + 64 * PSTRIDE)
#define SM_BYTES  (SM_FLOATS * 4)

__global__ __launch_bounds__(256, 1)
void attn_kernel(const float* __restrict__ y,
                 const int* __restrict__ mask,   // y_mask: bool materialized as int32
                 float* __restrict__ out)
{
    extern __shared__ float sm[];
    float* sXpT = sm;                       // [256][TSTRIDE]  (k-major)
    float* sYpT = sXpT + 256 * TSTRIDE;     // [256][TSTRIDE]
    float* sY   = sYpT + 256 * TSTRIDE;     // [64][256] natural layout
    float* sP   = sY + 64 * 256;            // [64][PSTRIDE]

    const int tid = threadIdx.x;
    const int tx = tid & 15;
    const int ty = tid >> 4;
    const int b  = blockIdx.y;
    const int x0 = blockIdx.x * 64;

    const float* __restrict__ xp  = g_xp + (size_t)(b * LXX + x0) * DD;
    const float* __restrict__ ypB = g_yp + (size_t)b * LYY * DD;
    const float* __restrict__ yB  = y    + (size_t)b * LYY * DD;
    const int* __restrict__ mB    = mask + (size_t)b * LYY;

    // Load Xp tile transposed: sXpT[k][r] = xp[r][k]. Lane = k => coalesced LDG.
#pragma unroll 8
    for (int e = 0; e < 64; e++)
        sXpT[tid * TSTRIDE + e] = xp[(size_t)e * DD + tid];

    float acc[4][16];
#pragma unroll
    for (int i = 0; i < 4; i++)
#pragma unroll
        for (int c = 0; c < 16; c++) acc[i][c] = 0.0f;

    float mrun[4], lrun[4];
#pragma unroll
    for (int i = 0; i < 4; i++) { mrun[i] = -1e30f; lrun[i] = 0.0f; }

    for (int t = 0; t < LYY / 64; t++) {
        const int j0 = t * 64;
        __syncthreads();  // protect smem tiles from previous iteration's readers

        // Load Yp tile transposed
#pragma unroll 8
        for (int e = 0; e < 64; e++)
            sYpT[tid * TSTRIDE + e] = ypB[(size_t)(j0 + e) * DD + tid];
        // Load raw Y tile, natural layout, float4
        const float4* ysrc = (const float4*)(yB + (size_t)j0 * DD);
#pragma unroll
        for (int e = 0; e < 16; e++) {
            int idx = tid + e * 256;      // float4 index within 64*64
            ((float4*)sY)[idx] = ysrc[idx];
        }
        __syncthreads();

        // ---- S = Xp @ Yp^T (4x4 per thread) ----
        float s[4][4];
#pragma unroll
        for (int i = 0; i < 4; i++)
#pragma unroll
            for (int j = 0; j < 4; j++) s[i][j] = 0.0f;

#pragma unroll 8
        for (int k = 0; k < 256; k++) {
            float4 a = *(const float4*)&sXpT[k * TSTRIDE + ty * 4];
            float4 v = *(const float4*)&sYpT[k * TSTRIDE + tx * 4];
            float av[4] = {a.x, a.y, a.z, a.w};
            float vv[4] = {v.x, v.y, v.z, v.w};
#pragma unroll
            for (int i = 0; i < 4; i++)
#pragma unroll
                for (int j = 0; j < 4; j++)
                    s[i][j] = fmaf(av[i], vv[j], s[i][j]);
        }

        // ---- mask (int32 bools; nonzero => exclude) ----
        int4 mk = *(const int4*)(mB + j0 + tx * 4);
        int mkb[4] = {mk.x, mk.y, mk.z, mk.w};
#pragma unroll
        for (int j = 0; j < 4; j++)
            if (mkb[j]) {
#pragma unroll
                for (int i = 0; i < 4; i++) s[i][j] = -3.0e38f;
            }

        // ---- online softmax (row groups = 16 lanes within a half-warp) ----
#pragma unroll
        for (int i = 0; i < 4; i++) {
            float m = fmaxf(fmaxf(s[i][0], s[i][1]), fmaxf(s[i][2], s[i][3]));
            m = fmaxf(m, __shfl_xor_sync(0xffffffffu, m, 1));
            m = fmaxf(m, __shfl_xor_sync(0xffffffffu, m, 2));
            m = fmaxf(m, __shfl_xor_sync(0xffffffffu, m, 4));
            m = fmaxf(m, __shfl_xor_sync(0xffffffffu, m, 8));
            float mnew  = fmaxf(mrun[i], m);
            float scale = __expf(mrun[i] - mnew);

            float p[4];
            float rs = 0.0f;
#pragma unroll
            for (int j = 0; j < 4; j++) {
                p[j] = __expf(s[i][j] - mnew);
                rs += p[j];
            }
            rs += __shfl_xor_sync(0xffffffffu, rs, 1);
            rs += __shfl_xor_sync(0xffffffffu, rs, 2);
            rs += __shfl_xor_sync(0xffffffffu, rs, 4);
            rs += __shfl_xor_sync(0xffffffffu, rs, 8);

            lrun[i] = lrun[i] * scale + rs;
            mrun[i] = mnew;

            *(float4*)&sP[(ty * 4 + i) * PSTRIDE + tx * 4] =
                make_float4(p[0], p[1], p[2], p[3]);

#pragma unroll
            for (int c = 0; c < 16; c++) acc[i][c] *= scale;
        }
        __syncwarp();  // sP rows for this warp written/read only within the warp

        // ---- acc += P @ Y (4x16 per thread) ----
#pragma unroll 4
        for (int j = 0; j < 64; j++) {
            float pj[4];
#pragma unroll
            for (int i = 0; i < 4; i++)
                pj[i] = sP[(ty * 4 + i) * PSTRIDE + j];
#pragma unroll
            for (int c = 0; c < 16; c++) {
                float yv = sY[j * 256 + c * 16 + tx];
#pragma unroll
                for (int i = 0; i < 4; i++)
                    acc[i][c] = fmaf(pj[i], yv, acc[i][c]);
            }
        }
    }

    // ---- normalize + store ----
#pragma unroll
    for (int i = 0; i < 4; i++) {
        float inv = 1.0f / lrun[i];
        float* dst = out + (size_t)(b * LXX + x0 + ty * 4 + i) * DD;
#pragma unroll
        for (int c = 0; c < 16; c++)
            dst[c * 16 + tx] = acc[i][c] * inv;
    }
}

// ---------------------------------------------------------------------------
extern "C" void kernel_launch(void* const* d_in, const int* in_sizes, int n_in,
                              void* d_out, int out_size)
{
    const float* x   = (const float*)d_in[0];
    const float* y   = (const float*)d_in[1];
    const int* mask  = (const int*)d_in[2];
    const float* W   = (const float*)d_in[3];
    const float* bias= (const float*)d_in[4];
    float* out       = (float*)d_out;

    // Projections: x -> g_xp, y -> g_yp
    proj_kernel<<<dim3(DD / 128, (BB * LXX) / 128), 256>>>(x, W, bias, 0);
    proj_kernel<<<dim3(DD / 128, (BB * LYY) / 128), 256>>>(y, W, bias, 1);

    // Fused attention
    cudaFuncSetAttribute(attn_kernel,
                         cudaFuncAttributeMaxDynamicSharedMemorySize, SM_BYTES);
    attn_kernel<<<dim3(LXX / 64, BB), 256, SM_BYTES>>>(y, mask, out);
}

// round 4
// speedup vs baseline: 2.6796x; 2.6796x over previous
#include <cuda_runtime.h>
#include <cuda_bf16.h>
#include <cstdint>

#define BB 8
#define LXX 2048
#define LYY 2048
#define DD 256

// ---------------- global scratch (no cudaMalloc allowed) ----------------
__device__ __nv_bfloat16 g_xp_h[BB * LXX * DD];
__device__ __nv_bfloat16 g_xp_l[BB * LXX * DD];
__device__ __nv_bfloat16 g_yp_h[BB * LYY * DD];
__device__ __nv_bfloat16 g_yp_l[BB * LYY * DD];
__device__ __nv_bfloat16 g_yv_h[BB * LYY * DD];   // raw y, bf16 hi
__device__ __nv_bfloat16 g_yv_l[BB * LYY * DD];   // raw y, bf16 lo

// ---------------- helpers (portable PTX only: sm_80-era) ----------------
__device__ __forceinline__ uint32_t smem_u32(const void* p) {
    uint32_t a;
    asm("{ .reg .u64 t; cvta.to.shared.u64 t, %1; cvt.u32.u64 %0, t; }" : "=r"(a) : "l"(p));
    return a;
}
__device__ __forceinline__ void cpa16(uint32_t s, const void* g) {
    asm volatile("cp.async.cg.shared.global [%0], [%1], 16;" :: "r"(s), "l"(g));
}
__device__ __forceinline__ void cpa4(uint32_t s, const void* g) {
    asm volatile("cp.async.ca.shared.global [%0], [%1], 4;" :: "r"(s), "l"(g));
}
#define CP_COMMIT() asm volatile("cp.async.commit_group;" ::: "memory")
#define CP_WAIT0()  asm volatile("cp.async.wait_group 0;" ::: "memory")

__device__ __forceinline__ void ldsm4(uint32_t r[4], uint32_t a) {
    asm volatile("ldmatrix.sync.aligned.m8n8.x4.shared.b16 {%0,%1,%2,%3}, [%4];"
                 : "=r"(r[0]), "=r"(r[1]), "=r"(r[2]), "=r"(r[3]) : "r"(a));
}
__device__ __forceinline__ void ldsm4t(uint32_t r[4], uint32_t a) {
    asm volatile("ldmatrix.sync.aligned.m8n8.x4.trans.shared.b16 {%0,%1,%2,%3}, [%4];"
                 : "=r"(r[0]), "=r"(r[1]), "=r"(r[2]), "=r"(r[3]) : "r"(a));
}
__device__ __forceinline__ void mma16816(float c[4], const uint32_t a[4],
                                         uint32_t b0, uint32_t b1) {
    asm volatile(
        "mma.sync.aligned.m16n8k16.row.col.f32.bf16.bf16.f32 "
        "{%0,%1,%2,%3}, {%4,%5,%6,%7}, {%8,%9}, {%0,%1,%2,%3};"
        : "+f"(c[0]), "+f"(c[1]), "+f"(c[2]), "+f"(c[3])
        : "r"(a[0]), "r"(a[1]), "r"(a[2]), "r"(a[3]), "r"(b0), "r"(b1));
}
// pack two f32 -> bf16x2 (lo = first arg)
__device__ __forceinline__ uint32_t cvt2bf(float lo, float hi) {
    uint32_t r;
    asm("cvt.rn.bf16x2.f32 %0, %1, %2;" : "=r"(r) : "f"(hi), "f"(lo));
    return r;
}
// exp2 via FMA-pipe polynomial (MUFU is 19x slower chip-wide); t clamped >= -126
__device__ __forceinline__ float exp2p(float t) {
    t = fmaxf(t, -126.0f);
    float n = rintf(t);
    float f = t - n;
    float p = fmaf(1.5403530e-4f, f, 1.3333558e-3f);
    p = fmaf(p, f, 9.6181290e-3f);
    p = fmaf(p, f, 5.5504109e-2f);
    p = fmaf(p, f, 2.4022651e-1f);
    p = fmaf(p, f, 6.9314718e-1f);
    p = fmaf(p, f, 1.0f);
    return p * __int_as_float(((int)n + 127) << 23);
}
#define L2E 1.4426950408889634f

// ---------------------------------------------------------------------------
// Projection (fp32 SIMT) -> bf16 hi/lo splits. C = relu(A @ W^T + b)
// ---------------------------------------------------------------------------
__global__ __launch_bounds__(256, 1)
void proj_kernel(const float* __restrict__ A,
                 const float* __restrict__ W,
                 const float* __restrict__ bias,
                 int which)
{
    __shared__ float As[16][132];
    __shared__ float Bs[16][132];

    const int tid = threadIdx.x;
    const int tx = tid & 15;
    const int ty = tid >> 4;
    const int row0 = blockIdx.y * 128;
    const int col0 = blockIdx.x * 128;

    __nv_bfloat16* __restrict__ Ch = which ? g_yp_h : g_xp_h;
    __nv_bfloat16* __restrict__ Cl = which ? g_yp_l : g_xp_l;

    float acc[8][8];
#pragma unroll
    for (int i = 0; i < 8; i++)
#pragma unroll
        for (int j = 0; j < 8; j++) acc[i][j] = 0.0f;

    for (int k0 = 0; k0 < DD; k0 += 16) {
#pragma unroll
        for (int e = 0; e < 8; e++) {
            int elem = tid + e * 256;
            int kk = elem & 15;
            int r  = elem >> 4;
            As[kk][r] = A[(size_t)(row0 + r) * DD + k0 + kk];
            Bs[kk][r] = W[(size_t)(col0 + r) * DD + k0 + kk];
        }
        __syncthreads();
#pragma unroll
        for (int kk = 0; kk < 16; kk++) {
            float4 a0 = *(const float4*)&As[kk][ty * 8];
            float4 a1 = *(const float4*)&As[kk][ty * 8 + 4];
            float4 b0 = *(const float4*)&Bs[kk][tx * 8];
            float4 b1 = *(const float4*)&Bs[kk][tx * 8 + 4];
            float a[8] = {a0.x, a0.y, a0.z, a0.w, a1.x, a1.y, a1.z, a1.w};
            float bq[8] = {b0.x, b0.y, b0.z, b0.w, b1.x, b1.y, b1.z, b1.w};
#pragma unroll
            for (int i = 0; i < 8; i++)
#pragma unroll
                for (int j = 0; j < 8; j++)
                    acc[i][j] = fmaf(a[i], bq[j], acc[i][j]);
        }
        __syncthreads();
    }

    float bv[8];
#pragma unroll
    for (int j = 0; j < 8; j++) bv[j] = bias[col0 + tx * 8 + j];

#pragma unroll
    for (int i = 0; i < 8; i++) {
        int row = row0 + ty * 8 + i;
        __nv_bfloat16 hb[8], lb[8];
#pragma unroll
        for (int j = 0; j < 8; j++) {
            float v = fmaxf(acc[i][j] + bv[j], 0.0f);
            __nv_bfloat16 h = __float2bfloat16_rn(v);
            hb[j] = h;
            lb[j] = __float2bfloat16_rn(v - __bfloat162float(h));
        }
        size_t o = (size_t)row * DD + col0 + tx * 8;
        *(uint4*)&Ch[o] = *(uint4*)hb;
        *(uint4*)&Cl[o] = *(uint4*)lb;
    }
}

// ---------------------------------------------------------------------------
// Elementwise y -> bf16 hi/lo (natural [b][tok][d] layout)
// ---------------------------------------------------------------------------
__global__ __launch_bounds__(256)
void split_y(const float* __restrict__ y)
{
    size_t i = ((size_t)blockIdx.x * 256 + threadIdx.x) * 4;
    float4 v = *(const float4*)(y + i);
    float vv[4] = {v.x, v.y, v.z, v.w};
    __nv_bfloat16 h[4], l[4];
#pragma unroll
    for (int k = 0; k < 4; k++) {
        h[k] = __float2bfloat16_rn(vv[k]);
        l[k] = __float2bfloat16_rn(vv[k] - __bfloat162float(h[k]));
    }
    *(uint2*)&g_yv_h[i] = *(uint2*)h;
    *(uint2*)&g_yv_l[i] = *(uint2*)l;
}

// ---------------------------------------------------------------------------
// Fused mma.sync attention.
// CTA = (b, 128 x-rows). 8 warps, warp = 16 rows, full D=256 in registers.
// LY streamed in 32-col tiles. 3-pass bf16 split per GEMM (hh + hl + lh).
// ---------------------------------------------------------------------------
#define SXSTR 528                       // 256 bf16 + 8 pad, bytes
#define SXH 0
#define SXL (SXH + 128 * SXSTR)
#define SBH (SXL + 128 * SXSTR)
#define SBL (SBH + 32 * SXSTR)
#define SVH (SBL + 32 * SXSTR)
#define SVL (SVH + 32 * SXSTR)
#define SMK (SVL + 32 * SXSTR)          // 32 ints
#define SMTOT (SMK + 128)

__global__ __launch_bounds__(256, 1)
void attn_mma_kernel(const int* __restrict__ mask, float* __restrict__ out)
{
    extern __shared__ char smc[];
    const uint32_t sa = smem_u32(smc);
    const int tid  = threadIdx.x;
    const int w    = tid >> 5;
    const int lane = tid & 31;
    const int lr   = lane >> 2;          // frag row within 8
    const int tig  = lane & 3;           // frag col pair
    const int b    = blockIdx.y;
    const int x0   = blockIdx.x * 128;
    const int rw   = w * 16;

    // ---- issue Xp tile loads (h+l), 128 rows x 512B ----
    {
        int r = tid >> 1;
        const __nv_bfloat16* srch = g_xp_h + (size_t)(b * LXX + x0 + r) * DD;
        const __nv_bfloat16* srcl = g_xp_l + (size_t)(b * LXX + x0 + r) * DD;
        uint32_t dh = sa + SXH + r * SXSTR;
        uint32_t dl = sa + SXL + r * SXSTR;
#pragma unroll
        for (int i = 0; i < 16; i++) {
            int c = (tid & 1) + 2 * i;
            cpa16(dh + c * 16, srch + c * 8);
            cpa16(dl + c * 16, srcl + c * 8);
        }
    }
    CP_COMMIT();

    const int* mB = mask + (size_t)b * LYY;
    const int* smk = (const int*)(smc + SMK);

    float O[32][4];
#pragma unroll
    for (int i = 0; i < 32; i++) { O[i][0] = O[i][1] = O[i][2] = O[i][3] = 0.f; }
    float m0 = -1e30f, m1 = -1e30f, l0 = 0.f, l1 = 0.f;

    // ldmatrix per-lane base addresses
    const uint32_t aA  = sa + SXH + (rw + (lane & 7) + ((lane >> 3) & 1) * 8) * SXSTR
                       + (lane >> 4) * 16;
    const uint32_t aAl = aA + (uint32_t)(SXL - SXH);
    const uint32_t aB  = sa + SBH + ((lane & 7) + ((lane < 16) ? 0 : 8)) * SXSTR
                       + ((lane >> 3) & 1) * 16;
    const uint32_t aBl = aB + (uint32_t)(SBL - SBH);
    const uint32_t aV  = sa + SVH + ((lane & 7) + ((lane >> 3) & 1) * 8) * SXSTR
                       + ((lane < 16) ? 0 : 16);
    const uint32_t aVl = aV + (uint32_t)(SVL - SVH);

    for (int t = 0; t < LYY / 32; t++) {
        const int j0 = t * 32;
        __syncthreads();                 // everyone done reading previous tile

        // ---- issue tile loads: Yp h/l, yV h/l, mask ----
        {
            int r = tid >> 3, cb = tid & 7;
            size_t gro = (size_t)(b * LYY + j0 + r) * DD;
            uint32_t o = r * SXSTR;
#pragma unroll
            for (int i = 0; i < 4; i++) {
                int c = cb + 8 * i;
                cpa16(sa + SBH + o + c * 16, g_yp_h + gro + c * 8);
                cpa16(sa + SBL + o + c * 16, g_yp_l + gro + c * 8);
                cpa16(sa + SVH + o + c * 16, g_yv_h + gro + c * 8);
                cpa16(sa + SVL + o + c * 16, g_yv_l + gro + c * 8);
            }
            if (tid < 32) cpa4(sa + SMK + tid * 4, mB + j0 + tid);
        }
        CP_COMMIT();
        CP_WAIT0();
        __syncthreads();

        // ---- S = Xp @ Yp^T (hh + hl + lh), 16 rows x 32 cols per warp ----
        float sf[4][4];
#pragma unroll
        for (int nt = 0; nt < 4; nt++)
#pragma unroll
            for (int i = 0; i < 4; i++) sf[nt][i] = 0.f;

#pragma unroll 4
        for (int kk = 0; kk < 16; kk++) {
            uint32_t ah[4], al[4], bh[4], bl[4];
            ldsm4(ah, aA  + kk * 32);
            ldsm4(al, aAl + kk * 32);
            // j 0..15
            ldsm4(bh, aB  + kk * 32);
            ldsm4(bl, aBl + kk * 32);
            mma16816(sf[0], ah, bh[0], bh[1]);
            mma16816(sf[0], ah, bl[0], bl[1]);
            mma16816(sf[0], al, bh[0], bh[1]);
            mma16816(sf[1], ah, bh[2], bh[3]);
            mma16816(sf[1], ah, bl[2], bl[3]);
            mma16816(sf[1], al, bh[2], bh[3]);
            // j 16..31
            ldsm4(bh, aB  + 16 * SXSTR + kk * 32);
            ldsm4(bl, aBl + 16 * SXSTR + kk * 32);
            mma16816(sf[2], ah, bh[0], bh[1]);
            mma16816(sf[2], ah, bl[0], bl[1]);
            mma16816(sf[2], al, bh[0], bh[1]);
            mma16816(sf[3], ah, bh[2], bh[3]);
            mma16816(sf[3], ah, bl[2], bl[3]);
            mma16816(sf[3], al, bh[2], bh[3]);
        }

        // ---- mask + online softmax ----
        float mx0 = -1e30f, mx1 = -1e30f;
#pragma unroll
        for (int nt = 0; nt < 4; nt++) {
            int j = 8 * nt + 2 * tig;
            if (smk[j])     { sf[nt][0] = -1e30f; sf[nt][2] = -1e30f; }
            if (smk[j + 1]) { sf[nt][1] = -1e30f; sf[nt][3] = -1e30f; }
            mx0 = fmaxf(mx0, fmaxf(sf[nt][0], sf[nt][1]));
            mx1 = fmaxf(mx1, fmaxf(sf[nt][2], sf[nt][3]));
        }
        mx0 = fmaxf(mx0, __shfl_xor_sync(0xffffffffu, mx0, 1));
        mx0 = fmaxf(mx0, __shfl_xor_sync(0xffffffffu, mx0, 2));
        mx1 = fmaxf(mx1, __shfl_xor_sync(0xffffffffu, mx1, 1));
        mx1 = fmaxf(mx1, __shfl_xor_sync(0xffffffffu, mx1, 2));

        float mn0 = fmaxf(m0, mx0), mn1 = fmaxf(m1, mx1);
        float sc0 = exp2p((m0 - mn0) * L2E);
        float sc1 = exp2p((m1 - mn1) * L2E);
        m0 = mn0; m1 = mn1;

        uint32_t ph[8], pl[8];
        float rs0 = 0.f, rs1 = 0.f;
#pragma unroll
        for (int nt = 0; nt < 4; nt++) {
            float p00 = exp2p((sf[nt][0] - mn0) * L2E);
            float p01 = exp2p((sf[nt][1] - mn0) * L2E);
            float p10 = exp2p((sf[nt][2] - mn1) * L2E);
            float p11 = exp2p((sf[nt][3] - mn1) * L2E);
            rs0 += p00 + p01;
            rs1 += p10 + p11;
            uint32_t h0 = cvt2bf(p00, p01);
            uint32_t h1 = cvt2bf(p10, p11);
            ph[nt * 2]     = h0;
            ph[nt * 2 + 1] = h1;
            float r00 = p00 - __uint_as_float(h0 << 16);
            float r01 = p01 - __uint_as_float(h0 & 0xffff0000u);
            float r10 = p10 - __uint_as_float(h1 << 16);
            float r11 = p11 - __uint_as_float(h1 & 0xffff0000u);
            pl[nt * 2]     = cvt2bf(r00, r01);
            pl[nt * 2 + 1] = cvt2bf(r10, r11);
        }
        rs0 += __shfl_xor_sync(0xffffffffu, rs0, 1);
        rs0 += __shfl_xor_sync(0xffffffffu, rs0, 2);
        rs1 += __shfl_xor_sync(0xffffffffu, rs1, 1);
        rs1 += __shfl_xor_sync(0xffffffffu, rs1, 2);
        l0 = l0 * sc0 + rs0;
        l1 = l1 * sc1 + rs1;

#pragma unroll
        for (int od = 0; od < 32; od++) {
            O[od][0] *= sc0; O[od][1] *= sc0;
            O[od][2] *= sc1; O[od][3] *= sc1;
        }

        // ---- O += P @ y  (Ph.Vh + Ph.Vl + Pl.Vh) ----
#pragma unroll
        for (int tp = 0; tp < 2; tp++) {
            const uint32_t* pA = ph + 4 * tp;
            const uint32_t* pL = pl + 4 * tp;
            uint32_t vb  = aV  + tp * 16 * SXSTR;
            uint32_t vbl = aVl + tp * 16 * SXSTR;
#pragma unroll
            for (int dg = 0; dg < 16; dg++) {
                uint32_t vh[4], vl[4];
                ldsm4t(vh, vb  + dg * 32);
                ldsm4t(vl, vbl + dg * 32);
                mma16816(O[2 * dg],     pA, vh[0], vh[1]);
                mma16816(O[2 * dg],     pA, vl[0], vl[1]);
                mma16816(O[2 * dg],     pL, vh[0], vh[1]);
                mma16816(O[2 * dg + 1], pA, vh[2], vh[3]);
                mma16816(O[2 * dg + 1], pA, vl[2], vl[3]);
                mma16816(O[2 * dg + 1], pL, vh[2], vh[3]);
            }
        }
    }

    // ---- epilogue: normalize + store ----
    float inv0 = 1.0f / l0, inv1 = 1.0f / l1;
    float* o0 = out + (size_t)(b * LXX + x0 + rw + lr) * DD;
    float* o1 = o0 + 8 * DD;
#pragma unroll
    for (int od = 0; od < 32; od++) {
        int c = od * 8 + tig * 2;
        *(float2*)(o0 + c) = make_float2(O[od][0] * inv0, O[od][1] * inv0);
        *(float2*)(o1 + c) = make_float2(O[od][2] * inv1, O[od][3] * inv1);
    }
}

// ---------------------------------------------------------------------------
extern "C" void kernel_launch(void* const* d_in, const int* in_sizes, int n_in,
                              void* d_out, int out_size)
{
    const float* x    = (const float*)d_in[0];
    const float* y    = (const float*)d_in[1];
    const int* mask   = (const int*)d_in[2];
    const float* W    = (const float*)d_in[3];
    const float* bias = (const float*)d_in[4];
    float* out        = (float*)d_out;

    split_y<<<(BB * LYY * DD) / (256 * 4), 256>>>(y);
    proj_kernel<<<dim3(DD / 128, (BB * LXX) / 128), 256>>>(x, W, bias, 0);
    proj_kernel<<<dim3(DD / 128, (BB * LYY) / 128), 256>>>(y, W, bias, 1);

    cudaFuncSetAttribute(attn_mma_kernel,
                         cudaFuncAttributeMaxDynamicSharedMemorySize, SMTOT);
    attn_mma_kernel<<<dim3(LXX / 128, BB), 256, SMTOT>>>(mask, out);
}